// round 13
// baseline (speedup 1.0000x reference)
#include <cuda_runtime.h>
#include <cuda_fp16.h>
#include <cstdint>

#define IN_F   4096
#define OUT_F  11008
#define M_MAX  8192
#define NGROUPS (OUT_F * (IN_F / 16))   // 2818048
#define DEQ_BLOCKS (NGROUPS / 256)      // 11008
#define CONV_BLOCKS ((M_MAX * IN_F / 8) / 256)   // 16384

// ---------------- scratch (static device arrays) ----------------
__device__ __align__(1024) __half g_wh[(size_t)OUT_F * IN_F];  // dequantized W, fp16
__device__ __align__(1024) __half g_xh[(size_t)M_MAX * IN_F];  // X, fp16

__device__ __forceinline__ uint32_t h2u(__half2 h) {
    union { __half2 h; uint32_t u; } c;
    c.h = h;
    return c.u;
}

// ---------------- kernel 1: merged pre-pass (dequant W + convert X) ----------
__global__ void prep_kernel(const int* __restrict__ Q, const float* __restrict__ NORM,
                            const float4* __restrict__ X) {
    int b = blockIdx.x;
    if (b < DEQ_BLOCKS) {
        size_t g = (size_t)b * 256 + threadIdx.x;
        const int4* qp = reinterpret_cast<const int4*>(Q + g * 8);
        int4 q0 = qp[0];
        int4 q1 = qp[1];
        float n = NORM[g];
        float s = n * (2.0f / 7.0f);
        int v[8] = {q0.x, q0.y, q0.z, q0.w, q1.x, q1.y, q1.z, q1.w};
        uint32_t h[8];
#pragma unroll
        for (int i = 0; i < 8; i++) {
            float w0 = fmaf((float)(v[i] & 7), s, -n);
            float w1 = fmaf((float)((v[i] >> 3) & 7), s, -n);
            h[i] = h2u(__floats2half2_rn(w0, w1));
        }
        uint4* dst = reinterpret_cast<uint4*>(g_wh + g * 16);
        uint4 o0, o1;
        o0.x = h[0]; o0.y = h[1]; o0.z = h[2]; o0.w = h[3];
        o1.x = h[4]; o1.y = h[5]; o1.z = h[6]; o1.w = h[7];
        dst[0] = o0;
        dst[1] = o1;
    } else {
        size_t i = (size_t)(b - DEQ_BLOCKS) * 256 + threadIdx.x;  // 8 floats each
        float4 v0 = X[2 * i];
        float4 v1 = X[2 * i + 1];
        uint4 o;
        o.x = h2u(__floats2half2_rn(v0.x, v0.y));
        o.y = h2u(__floats2half2_rn(v0.z, v0.w));
        o.z = h2u(__floats2half2_rn(v1.x, v1.y));
        o.w = h2u(__floats2half2_rn(v1.z, v1.w));
        reinterpret_cast<uint4*>(g_xh)[i] = o;
    }
}

// ---------------- kernel 2: persistent pipelined fp16 mma GEMM, 2 CTAs/SM ----
// CTA tile 128(M) x 128(N) x 64(K halves), 256 threads = 8 warps in 2(M) x 4(N),
// warp tile 64 x 32. 3 stages x 32 KB, single __syncthreads/iter (r10 mainloop).
// r13: persistent CTAs (grid = 2*SMs) looping over tiles; next tile's 2-stage
// prologue issued BEFORE the epilogue stores so the fill rides the epilogue.
#define BM 128
#define BN 128
#define BKH 64
#define ROWW 32
#define STAGES 3
#define A_WORDS (BM * ROWW)                      // 4096
#define B_WORDS (BN * ROWW)                      // 4096
#define STAGE_WORDS (A_WORDS + B_WORDS)          // 8192 words = 32 KB
#define SMEM_BYTES (STAGES * STAGE_WORDS * 4)    // 96 KB
#define NKT (IN_F / BKH)                          // 64
#define NTH 256

__device__ __forceinline__ void cp16(uint32_t dst, const void* src) {
    asm volatile("cp.async.cg.shared.global [%0], [%1], 16;" :: "r"(dst), "l"(src));
}

__device__ __forceinline__ void ldsm4(uint32_t* r, uint32_t addr) {
    asm volatile("ldmatrix.sync.aligned.m8n8.x4.shared.b16 {%0,%1,%2,%3}, [%4];"
        : "=r"(r[0]), "=r"(r[1]), "=r"(r[2]), "=r"(r[3]) : "r"(addr));
}

__device__ __forceinline__ void mma_f16(float* d, const uint32_t* a, const uint32_t* b) {
    asm volatile(
        "mma.sync.aligned.m16n8k16.row.col.f32.f16.f16.f32 "
        "{%0,%1,%2,%3}, {%4,%5,%6,%7}, {%8,%9}, {%0,%1,%2,%3};"
        : "+f"(d[0]), "+f"(d[1]), "+f"(d[2]), "+f"(d[3])
        : "r"(a[0]), "r"(a[1]), "r"(a[2]), "r"(a[3]),
          "r"(b[0]), "r"(b[1]));
}

__global__ __launch_bounds__(NTH, 2)
void gemm_mma_f16(const __half* __restrict__ A,     // g_xh [M, K]
                  const __half* __restrict__ B,     // g_wh [N, K]
                  const float* __restrict__ bias,
                  float* __restrict__ C,
                  int mtiles)
{
    extern __shared__ __align__(1024) uint32_t smw[];
    const int tid  = threadIdx.x;
    const int lane = tid & 31;
    const int warp = tid >> 5;
    const int wm   = warp & 1;          // M dir: 64 rows each
    const int wn   = warp >> 1;         // N dir: 32 cols each

    const int NT = OUT_F / BN;          // 86
    const int GM = 8;
    const int total = 0;                // placeholder silenced below
    (void)total;
    const int ntiles_total = (M_MAX / BM) * NT;  // mtiles==64 always; keep static
    const int real_total = mtiles * NT;

    const int lrow = tid >> 3;          // 0..31
    const int lkc  = tid & 7;
    const uint32_t s_base = (uint32_t)__cvta_generic_to_shared(smw);

    // ---- ldmatrix per-lane address components (derivation verified r7/r8) ----
    const int p  = lane >> 3;           // matrix part 0..3
    const int rl = lane & 7;            // row within 8-row matrix
    const int a_cbit = p >> 1;
    const int a_roff = rl + (p & 1) * 8;
    const int b_cbit = p & 1;
    const int b_roff = rl + (p >> 1) * 8;

    uint32_t a_rowb[4], b_rowb[2];
#pragma unroll
    for (int mi = 0; mi < 4; mi++) a_rowb[mi] = (uint32_t)(wm * 64 + mi * 16 + a_roff) * 128;
#pragma unroll
    for (int nj = 0; nj < 2; nj++) b_rowb[nj] = (uint32_t)(wn * 32 + nj * 16 + b_roff) * 128;

    // ---- raster: tile index -> (m0, n0) (GM-grouped, identical to r10) ----
#define RASTER(tileidx, m0v, n0v) do {                                            \
    int grp_   = (tileidx) / (GM * NT);                                           \
    int first_ = grp_ * GM;                                                       \
    int gsz_   = (mtiles - first_ < GM) ? (mtiles - first_) : GM;                  \
    int rem_   = (tileidx) - grp_ * GM * NT;                                      \
    (m0v) = (first_ + rem_ % gsz_) * BM;                                          \
    (n0v) = (rem_ / gsz_) * BN;                                                   \
} while (0)

#define LOAD_TILE(stg, kt) do {                                                   \
    uint32_t sa = s_base + (uint32_t)((stg) * STAGE_WORDS) * 4;                   \
    uint32_t sb = sa + A_WORDS * 4;                                               \
    _Pragma("unroll")                                                             \
    for (int i = 0; i < 4; i++) {                                                 \
        int row = lrow + i * 32;                                                  \
        uint32_t schunk = (uint32_t)(lkc ^ (row & 7));                            \
        cp16(sa + (uint32_t)(row * ROWW + schunk * 4) * 4,                        \
             gA + (size_t)row * IN_F + (kt) * BKH + lkc * 8);                     \
    }                                                                             \
    _Pragma("unroll")                                                             \
    for (int i = 0; i < 4; i++) {                                                 \
        int row = lrow + i * 32;                                                  \
        uint32_t schunk = (uint32_t)(lkc ^ (row & 7));                            \
        cp16(sb + (uint32_t)(row * ROWW + schunk * 4) * 4,                        \
             gB + (size_t)row * IN_F + (kt) * BKH + lkc * 8);                     \
    }                                                                             \
    asm volatile("cp.async.commit_group;");                                       \
} while (0)

    uint32_t af[4][4], bf[2][4];

#define LD_FRAGS(ks, sAb, sBb) do {                                               \
    uint32_t asw = (uint32_t)(((2 * (ks) + a_cbit) ^ rl) << 4);                   \
    uint32_t bsw = (uint32_t)(((2 * (ks) + b_cbit) ^ rl) << 4);                   \
    _Pragma("unroll")                                                             \
    for (int mi = 0; mi < 4; mi++) ldsm4(af[mi], (sAb) + a_rowb[mi] + asw);       \
    _Pragma("unroll")                                                             \
    for (int nj = 0; nj < 2; nj++) ldsm4(bf[nj], (sBb) + b_rowb[nj] + bsw);       \
} while (0)

    int tile = blockIdx.x;
    if (tile >= real_total) return;

    int m0, n0;
    RASTER(tile, m0, n0);
    const __half* gA = A + (size_t)m0 * IN_F;
    const __half* gB = B + (size_t)n0 * IN_F;

    // prologue for first tile: stages 0..1
#pragma unroll
    for (int s = 0; s < STAGES - 1; s++) LOAD_TILE(s, s);

    const int g   = lane >> 2;
    const int tig = lane & 3;

    while (true) {
        float acc[4][4][4];
#pragma unroll
        for (int mi = 0; mi < 4; mi++)
#pragma unroll
            for (int ni = 0; ni < 4; ni++)
#pragma unroll
                for (int q = 0; q < 4; q++) acc[mi][ni][q] = 0.0f;

        for (int t = 0; t < NKT; t++) {
            asm volatile("cp.async.wait_group %0;" :: "n"(STAGES - 2));
            __syncthreads();

            const uint32_t sAb = s_base + (uint32_t)((t % STAGES) * STAGE_WORDS) * 4;
            const uint32_t sBb = sAb + A_WORDS * 4;

            int nxt = t + STAGES - 1;
            if (nxt < NKT) {
                LOAD_TILE(nxt % STAGES, nxt);
            } else {
                asm volatile("cp.async.commit_group;");
            }

#pragma unroll
            for (int ks = 0; ks < 4; ks++) {
                LD_FRAGS(ks, sAb, sBb);
#pragma unroll
                for (int mi = 0; mi < 4; mi++)
#pragma unroll
                    for (int ni = 0; ni < 4; ni++)
                        mma_f16(acc[mi][ni], af[mi], &bf[ni >> 1][(ni & 1) * 2]);
            }
        }

        // ---- transition: issue next tile's prologue BEFORE the epilogue ----
        const int om0 = m0, on0 = n0;
        const int ntile = tile + (int)gridDim.x;
        const bool more = (ntile < real_total);
        if (more) {
            RASTER(ntile, m0, n0);
            gA = A + (size_t)m0 * IN_F;
            gB = B + (size_t)n0 * IN_F;
            __syncthreads();   // all warps done reading old stages (WAR)
#pragma unroll
            for (int s = 0; s < STAGES - 1; s++) LOAD_TILE(s, s);
        }

        // ---- epilogue: bias + store (overlaps the new prologue's cp.asyncs) ----
#pragma unroll
        for (int mi = 0; mi < 4; mi++) {
            const int row = om0 + wm * 64 + mi * 16 + g;
            float* c0 = C + (size_t)row * OUT_F;
            float* c1 = C + (size_t)(row + 8) * OUT_F;
#pragma unroll
            for (int ni = 0; ni < 4; ni++) {
                const int col = on0 + wn * 32 + ni * 8 + tig * 2;
                float2 bv = *reinterpret_cast<const float2*>(bias + col);
                float2 o0, o1;
                o0.x = acc[mi][ni][0] + bv.x;
                o0.y = acc[mi][ni][1] + bv.y;
                o1.x = acc[mi][ni][2] + bv.x;
                o1.y = acc[mi][ni][3] + bv.y;
                *reinterpret_cast<float2*>(c0 + col) = o0;
                *reinterpret_cast<float2*>(c1 + col) = o1;
            }
        }

        if (!more) break;
        tile = ntile;
    }
}

// ---------------- host launcher ----------------
extern "C" void kernel_launch(void* const* d_in, const int* in_sizes, int n_in,
                              void* d_out, int out_size)
{
    const float* x    = (const float*)d_in[0];
    const int*   q3   = (const int*)  d_in[1];
    const float* nrm  = (const float*)d_in[2];
    const float* bias = (const float*)d_in[3];
    float* out = (float*)d_out;

    const int M = in_sizes[0] / IN_F;            // 8192

    void* wptr = nullptr; cudaGetSymbolAddress(&wptr, g_wh);
    void* xptr = nullptr; cudaGetSymbolAddress(&xptr, g_xh);

    prep_kernel<<<DEQ_BLOCKS + CONV_BLOCKS, 256>>>(
        q3, nrm, reinterpret_cast<const float4*>(x));

    cudaFuncSetAttribute(gemm_mma_f16,
                         cudaFuncAttributeMaxDynamicSharedMemorySize, SMEM_BYTES);

    int smCount = 148;
    cudaDeviceGetAttribute(&smCount, cudaDevAttrMultiProcessorCount, 0);
    const int mtiles = M / BM;                   // 64
    const int grid = 2 * smCount;                // persistent: 2 CTAs per SM
    gemm_mma_f16<<<grid, NTH, SMEM_BYTES>>>((const __half*)xptr, (const __half*)wptr,
                                            bias, out, mtiles);
}

// round 14
// speedup vs baseline: 1.0668x; 1.0668x over previous
#include <cuda_runtime.h>
#include <cuda_fp16.h>
#include <cstdint>

#define IN_F   4096
#define OUT_F  11008
#define M_MAX  8192
#define NGROUPS (OUT_F * (IN_F / 16))   // 2818048
#define DEQ_BLOCKS (NGROUPS / 256)      // 11008
#define CONV_BLOCKS ((M_MAX * IN_F / 8) / 256)   // 16384

// ---------------- scratch (static device arrays) ----------------
__device__ __align__(1024) __half g_wh[(size_t)OUT_F * IN_F];  // dequantized W, fp16
__device__ __align__(1024) __half g_xh[(size_t)M_MAX * IN_F];  // X, fp16

__device__ __forceinline__ uint32_t h2u(__half2 h) {
    union { __half2 h; uint32_t u; } c;
    c.h = h;
    return c.u;
}

// ---------------- kernel 1: merged pre-pass (dequant W + convert X) ----------
__global__ void prep_kernel(const int* __restrict__ Q, const float* __restrict__ NORM,
                            const float4* __restrict__ X) {
    int b = blockIdx.x;
    if (b < DEQ_BLOCKS) {
        size_t g = (size_t)b * 256 + threadIdx.x;
        const int4* qp = reinterpret_cast<const int4*>(Q + g * 8);
        int4 q0 = qp[0];
        int4 q1 = qp[1];
        float n = NORM[g];
        float s = n * (2.0f / 7.0f);
        int v[8] = {q0.x, q0.y, q0.z, q0.w, q1.x, q1.y, q1.z, q1.w};
        uint32_t h[8];
#pragma unroll
        for (int i = 0; i < 8; i++) {
            float w0 = fmaf((float)(v[i] & 7), s, -n);
            float w1 = fmaf((float)((v[i] >> 3) & 7), s, -n);
            h[i] = h2u(__floats2half2_rn(w0, w1));
        }
        uint4* dst = reinterpret_cast<uint4*>(g_wh + g * 16);
        uint4 o0, o1;
        o0.x = h[0]; o0.y = h[1]; o0.z = h[2]; o0.w = h[3];
        o1.x = h[4]; o1.y = h[5]; o1.z = h[6]; o1.w = h[7];
        dst[0] = o0;
        dst[1] = o1;
    } else {
        size_t i = (size_t)(b - DEQ_BLOCKS) * 256 + threadIdx.x;  // 8 floats each
        float4 v0 = X[2 * i];
        float4 v1 = X[2 * i + 1];
        uint4 o;
        o.x = h2u(__floats2half2_rn(v0.x, v0.y));
        o.y = h2u(__floats2half2_rn(v0.z, v0.w));
        o.z = h2u(__floats2half2_rn(v1.x, v1.y));
        o.w = h2u(__floats2half2_rn(v1.z, v1.w));
        reinterpret_cast<uint4*>(g_xh)[i] = o;
    }
}

// ---------------- kernel 2: pipelined fp16 mma GEMM, 2 CTAs/SM --------------
// CTA tile 128(M) x 128(N) x 64(K halves), 256 threads = 8 warps in 2(M) x 4(N),
// warp tile 64 x 32. 3 stages x 32 KB = 96 KB/CTA, single __syncthreads/iter.
// r14 = r10 + unroll-3 mainloop (compile-time stage offsets) + precomputed
// swizzle offsets asw/bsw (removes per-iter address ALU).
#define BM 128
#define BN 128
#define BKH 64
#define ROWW 32
#define STAGES 3
#define A_WORDS (BM * ROWW)                      // 4096
#define B_WORDS (BN * ROWW)                      // 4096
#define STAGE_WORDS (A_WORDS + B_WORDS)          // 8192 words = 32 KB
#define SMEM_BYTES (STAGES * STAGE_WORDS * 4)    // 96 KB
#define NKT (IN_F / BKH)                          // 64
#define NTH 256

__device__ __forceinline__ void cp16(uint32_t dst, const void* src) {
    asm volatile("cp.async.cg.shared.global [%0], [%1], 16;" :: "r"(dst), "l"(src));
}

__device__ __forceinline__ void ldsm4(uint32_t* r, uint32_t addr) {
    asm volatile("ldmatrix.sync.aligned.m8n8.x4.shared.b16 {%0,%1,%2,%3}, [%4];"
        : "=r"(r[0]), "=r"(r[1]), "=r"(r[2]), "=r"(r[3]) : "r"(addr));
}

__device__ __forceinline__ void mma_f16(float* d, const uint32_t* a, const uint32_t* b) {
    asm volatile(
        "mma.sync.aligned.m16n8k16.row.col.f32.f16.f16.f32 "
        "{%0,%1,%2,%3}, {%4,%5,%6,%7}, {%8,%9}, {%0,%1,%2,%3};"
        : "+f"(d[0]), "+f"(d[1]), "+f"(d[2]), "+f"(d[3])
        : "r"(a[0]), "r"(a[1]), "r"(a[2]), "r"(a[3]),
          "r"(b[0]), "r"(b[1]));
}

__global__ __launch_bounds__(NTH, 2)
void gemm_mma_f16(const __half* __restrict__ A,     // g_xh [M, K]
                  const __half* __restrict__ B,     // g_wh [N, K]
                  const float* __restrict__ bias,
                  float* __restrict__ C,
                  int mtiles)
{
    extern __shared__ __align__(1024) uint32_t smw[];
    const int tid  = threadIdx.x;
    const int lane = tid & 31;
    const int warp = tid >> 5;
    const int wm   = warp & 1;          // M dir: 64 rows each
    const int wn   = warp >> 1;         // N dir: 32 cols each

    // ---- grouped rasterization (GM=8) ----
    const int NT = OUT_F / BN;          // 86
    const int GM = 8;
    int bid   = blockIdx.x;
    int grp   = bid / (GM * NT);
    int first = grp * GM;
    int gsz   = (mtiles - first < GM) ? (mtiles - first) : GM;
    int rem   = bid - grp * GM * NT;
    int mt    = first + rem % gsz;
    int nt    = rem / gsz;
    const int m0 = mt * BM;
    const int n0 = nt * BN;

    const __half* gA = A + (size_t)m0 * IN_F;
    const __half* gB = B + (size_t)n0 * IN_F;

    const int lrow = tid >> 3;          // 0..31
    const int lkc  = tid & 7;
    const uint32_t s_base = (uint32_t)__cvta_generic_to_shared(smw);

    // ---- ldmatrix per-lane address components (derivation verified r7/r8) ----
    const int p  = lane >> 3;           // matrix part 0..3
    const int rl = lane & 7;            // row within 8-row matrix
    const int a_cbit = p >> 1;
    const int a_roff = rl + (p & 1) * 8;
    const int b_cbit = p & 1;
    const int b_roff = rl + (p >> 1) * 8;

    uint32_t a_rowb[4], b_rowb[2];
#pragma unroll
    for (int mi = 0; mi < 4; mi++) a_rowb[mi] = (uint32_t)(wm * 64 + mi * 16 + a_roff) * 128;
#pragma unroll
    for (int nj = 0; nj < 2; nj++) b_rowb[nj] = (uint32_t)(wn * 32 + nj * 16 + b_roff) * 128;

    // precomputed swizzle offsets per ks (loop-invariant)
    uint32_t aswk[4], bswk[4];
#pragma unroll
    for (int ks = 0; ks < 4; ks++) {
        aswk[ks] = (uint32_t)(((2 * ks + a_cbit) ^ rl) << 4);
        bswk[ks] = (uint32_t)(((2 * ks + b_cbit) ^ rl) << 4);
    }

    float acc[4][4][4];
#pragma unroll
    for (int mi = 0; mi < 4; mi++)
#pragma unroll
        for (int ni = 0; ni < 4; ni++)
#pragma unroll
            for (int q = 0; q < 4; q++) acc[mi][ni][q] = 0.0f;

#define LOAD_TILE(stg, kt) do {                                                   \
    uint32_t sa = s_base + (uint32_t)((stg) * STAGE_WORDS) * 4;                   \
    uint32_t sb = sa + A_WORDS * 4;                                               \
    _Pragma("unroll")                                                             \
    for (int i = 0; i < 4; i++) {                                                 \
        int row = lrow + i * 32;                                                  \
        uint32_t schunk = (uint32_t)(lkc ^ (row & 7));                            \
        cp16(sa + (uint32_t)(row * ROWW + schunk * 4) * 4,                        \
             gA + (size_t)row * IN_F + (kt) * BKH + lkc * 8);                     \
    }                                                                             \
    _Pragma("unroll")                                                             \
    for (int i = 0; i < 4; i++) {                                                 \
        int row = lrow + i * 32;                                                  \
        uint32_t schunk = (uint32_t)(lkc ^ (row & 7));                            \
        cp16(sb + (uint32_t)(row * ROWW + schunk * 4) * 4,                        \
             gB + (size_t)row * IN_F + (kt) * BKH + lkc * 8);                     \
    }                                                                             \
    asm volatile("cp.async.commit_group;");                                       \
} while (0)

    uint32_t af[4][4], bf[2][4];

#define LD_FRAGS(ks, sAb, sBb) do {                                               \
    _Pragma("unroll")                                                             \
    for (int mi = 0; mi < 4; mi++) ldsm4(af[mi], (sAb) + a_rowb[mi] + aswk[ks]);  \
    _Pragma("unroll")                                                             \
    for (int nj = 0; nj < 2; nj++) ldsm4(bf[nj], (sBb) + b_rowb[nj] + bswk[ks]);  \
} while (0)

    // prologue: stages 0..1
#pragma unroll
    for (int s = 0; s < STAGES - 1; s++) LOAD_TILE(s, s);

#pragma unroll 3
    for (int t = 0; t < NKT; t++) {
        asm volatile("cp.async.wait_group %0;" :: "n"(STAGES - 2));
        __syncthreads();   // single barrier per iter (stage rewritten was read last iter)

        const uint32_t sAb = s_base + (uint32_t)((t % STAGES) * STAGE_WORDS) * 4;
        const uint32_t sBb = sAb + A_WORDS * 4;

        int nxt = t + STAGES - 1;
        if (nxt < NKT) {
            LOAD_TILE(nxt % STAGES, nxt);
        } else {
            asm volatile("cp.async.commit_group;");
        }

#pragma unroll
        for (int ks = 0; ks < 4; ks++) {
            LD_FRAGS(ks, sAb, sBb);
#pragma unroll
            for (int mi = 0; mi < 4; mi++)
#pragma unroll
                for (int ni = 0; ni < 4; ni++)
                    mma_f16(acc[mi][ni], af[mi], &bf[ni >> 1][(ni & 1) * 2]);
        }
    }

    // ---- epilogue: bias + store ----
    const int g = lane >> 2;
    const int tig = lane & 3;
#pragma unroll
    for (int mi = 0; mi < 4; mi++) {
        const int row = m0 + wm * 64 + mi * 16 + g;
        float* c0 = C + (size_t)row * OUT_F;
        float* c1 = C + (size_t)(row + 8) * OUT_F;
#pragma unroll
        for (int ni = 0; ni < 4; ni++) {
            const int col = n0 + wn * 32 + ni * 8 + tig * 2;
            float2 bv = *reinterpret_cast<const float2*>(bias + col);
            float2 o0, o1;
            o0.x = acc[mi][ni][0] + bv.x;
            o0.y = acc[mi][ni][1] + bv.y;
            o1.x = acc[mi][ni][2] + bv.x;
            o1.y = acc[mi][ni][3] + bv.y;
            *reinterpret_cast<float2*>(c0 + col) = o0;
            *reinterpret_cast<float2*>(c1 + col) = o1;
        }
    }
}

// ---------------- host launcher ----------------
extern "C" void kernel_launch(void* const* d_in, const int* in_sizes, int n_in,
                              void* d_out, int out_size)
{
    const float* x    = (const float*)d_in[0];
    const int*   q3   = (const int*)  d_in[1];
    const float* nrm  = (const float*)d_in[2];
    const float* bias = (const float*)d_in[3];
    float* out = (float*)d_out;

    const int M = in_sizes[0] / IN_F;            // 8192

    void* wptr = nullptr; cudaGetSymbolAddress(&wptr, g_wh);
    void* xptr = nullptr; cudaGetSymbolAddress(&xptr, g_xh);

    prep_kernel<<<DEQ_BLOCKS + CONV_BLOCKS, 256>>>(
        q3, nrm, reinterpret_cast<const float4*>(x));

    cudaFuncSetAttribute(gemm_mma_f16,
                         cudaFuncAttributeMaxDynamicSharedMemorySize, SMEM_BYTES);
    const int mtiles = M / BM;                   // 64
    const int grid = mtiles * (OUT_F / BN);      // 64 * 86 = 5504
    gemm_mma_f16<<<grid, NTH, SMEM_BYTES>>>((const __half*)xptr, (const __half*)wptr,
                                            bias, out, mtiles);
}